// round 3
// baseline (speedup 1.0000x reference)
#include <cuda_runtime.h>
#include <math.h>

#define QD 256    // queries
#define II 2048   // gallery images
#define DD 256    // feature dim

#define BQ 64
#define BI 64
#define KC 16
#define QPITCH 18   // u64 per smem row (16 pairs + pad), 144B rows (16B aligned)
#define GPITCH 68   // floats per smem row (272B, 16B aligned)

typedef unsigned long long u64;

// ---- scratch (__device__ globals; no allocation allowed) ----
__device__ float d_C [QD * DD];   // fqn*A        natural [Q][D]
__device__ float d_A2[QD * DD];   // A^2          natural [Q][D]
__device__ float d_AB[QD * DD];   // 2*A*B        natural [Q][D]
__device__ float d_GT[DD * II];   // normalized gallery, transposed [D][I]
__device__ float d_c0[QD];
__device__ float d_b0;

// ---------------- packed f32x2 helpers ----------------
__device__ __forceinline__ u64 pack2(float lo, float hi) {
    u64 r;
    asm("mov.b64 %0, {%1, %2};" : "=l"(r) : "f"(lo), "f"(hi));
    return r;
}
__device__ __forceinline__ void unpack2(u64 v, float& lo, float& hi) {
    asm("mov.b64 {%0, %1}, %2;" : "=f"(lo), "=f"(hi) : "l"(v));
}
#define FMA2(acc, a, b) \
    asm("fma.rn.f32x2 %0, %1, %2, %0;" : "+l"(acc) : "l"(a), "l"(b))

__device__ __forceinline__ float warpSum(float v) {
    #pragma unroll
    for (int o = 16; o; o >>= 1) v += __shfl_xor_sync(0xffffffffu, v, o);
    return v;
}

// ---------------- fused prep kernel: 64 blocks x 256 threads ----------------
// blocks 0..31  : gallery normalize + transpose (64 rows each)
// blocks 32..63 : query precompute, warp-per-query (8 queries each)
__global__ __launch_bounds__(256) void prep_kernel(
        const float* __restrict__ qf,
        const float* __restrict__ qi,
        const float* __restrict__ gal,
        const float* __restrict__ gamma,
        const float* __restrict__ beta,
        const float* __restrict__ mean,
        const float* __restrict__ var) {
    const int bx  = blockIdx.x;
    const int tid = threadIdx.x;

    if (bx < 32) {
        // ---- gallery part: rows i0..i0+63 ----
        __shared__ float sInv[64];
        __shared__ float sT[32][65];   // transpose staging, conflict-free
        const int i0 = bx * 64;
        const int w = tid >> 5, lane = tid & 31;

        // phase 1: per-row inverse norms (warp handles 8 rows sequentially)
        #pragma unroll
        for (int r = 0; r < 8; r++) {
            int il = w * 8 + r;
            const float4* row = (const float4*)&gal[(i0 + il) * DD];
            float4 a = row[lane];
            float4 b = row[lane + 32];
            float ss = a.x*a.x + a.y*a.y + a.z*a.z + a.w*a.w
                     + b.x*b.x + b.y*b.y + b.z*b.z + b.w*b.w;
            ss = warpSum(ss);
            if (lane == 0) sInv[il] = 1.f / fmaxf(sqrtf(ss), 1e-12f);
        }
        __syncthreads();

        // phase 2: transpose 32-d chunks through smem (all GMEM coalesced)
        for (int dc = 0; dc < DD; dc += 32) {
            #pragma unroll
            for (int it = 0; it < 2; it++) {
                int p  = tid + it * 256;
                int il = p >> 3;       // 0..63
                int kv = p & 7;        // 0..7 (d-subchunk of 4)
                float inv = sInv[il];
                float4 v = *(const float4*)&gal[(i0 + il) * DD + dc + 4 * kv];
                sT[4*kv + 0][il] = v.x * inv;
                sT[4*kv + 1][il] = v.y * inv;
                sT[4*kv + 2][il] = v.z * inv;
                sT[4*kv + 3][il] = v.w * inv;
            }
            __syncthreads();
            #pragma unroll
            for (int half = 0; half < 2; half++) {
                int dl = (tid >> 4) + 16 * half;  // 0..31
                int iv = tid & 15;                // 0..15
                float4 o;
                o.x = sT[dl][4*iv + 0];
                o.y = sT[dl][4*iv + 1];
                o.z = sT[dl][4*iv + 2];
                o.w = sT[dl][4*iv + 3];
                *(float4*)&d_GT[(dc + dl) * II + i0 + 4 * iv] = o;
            }
            __syncthreads();
        }
    } else {
        // ---- query part: warp per query, coalesced natural-layout stores ----
        const int q    = (bx - 32) * 8 + (tid >> 5);
        const int lane = tid & 31;

        float x[8], y[8], istd[8], B[8];
        float xs = 0.f, ys = 0.f;
        #pragma unroll
        for (int j = 0; j < 8; j++) {
            int d = lane + 32 * j;
            x[j] = qf[q * DD + d];
            y[j] = qi[q * DD + d];
            istd[j] = gamma[d] * rsqrtf(var[d] + 1e-5f);
            B[j] = beta[d] - mean[d] * istd[j];
            xs += x[j] * x[j];
            ys += y[j] * y[j];
        }
        xs = warpSum(xs);
        ys = warpSum(ys);
        float xin = 1.f / fmaxf(sqrtf(xs), 1e-12f);
        float yin = 1.f / fmaxf(sqrtf(ys), 1e-12f);

        float A[8], fq[8];
        float fs = 0.f;
        #pragma unroll
        for (int j = 0; j < 8; j++) {
            float xn = x[j] * xin;
            float gate = 1.f / (1.f + __expf(-xn * 5.0f));  // sigmoid(xn/0.2)
            A[j] = gate * istd[j];
            float yn = y[j] * yin;
            fq[j] = yn * A[j] + B[j];
            fs += fq[j] * fq[j];
        }
        fs = warpSum(fs);
        float fin = 1.f / fmaxf(sqrtf(fs), 1e-12f);

        float c0 = 0.f;
        #pragma unroll
        for (int j = 0; j < 8; j++) {
            int d = lane + 32 * j;
            float fqn = fq[j] * fin;
            d_C [q * DD + d] = fqn * A[j];
            d_A2[q * DD + d] = A[j] * A[j];
            d_AB[q * DD + d] = 2.f * A[j] * B[j];
            c0 += fqn * B[j];
        }
        c0 = warpSum(c0);
        if (lane == 0) d_c0[q] = c0;

        if (q == 0) {
            float b0 = 0.f;
            #pragma unroll
            for (int j = 0; j < 8; j++) b0 += B[j] * B[j];
            b0 = warpSum(b0);
            if (lane == 0) d_b0 = b0;
        }
    }
}

// ---------------- main scoring kernel ----------------
// grid (II/BI, QD/BQ) = (32, 4), block 256
__global__ __launch_bounds__(256) void score_kernel(float* __restrict__ out) {
    __shared__ u64  sC [BQ][QPITCH];   // pre-duplicated f32x2 pairs, [q][kc]
    __shared__ u64  sA2[BQ][QPITCH];
    __shared__ u64  sAB[BQ][QPITCH];
    __shared__ float sG [KC][GPITCH];  // [kc][i]
    __shared__ float sG2[KC][GPITCH];  // g^2, precomputed at load

    const int tid = threadIdx.x;
    const int tx = tid & 15;   // i direction (4 floats = 2 pairs)
    const int ty = tid >> 4;   // q direction (4 rows)
    const int i0 = blockIdx.x * BI;
    const int q0 = blockIdx.y * BQ;

    u64 s1[4][2], s2[4][2];
    #pragma unroll
    for (int u = 0; u < 4; u++) {
        s1[u][0] = 0ull; s1[u][1] = 0ull;
        s2[u][0] = 0ull; s2[u][1] = 0ull;
    }

    const int lq  = tid >> 2;  // 0..63 : q row for tile load
    const int lkv = tid & 3;   // 0..3  : float4 index along k
    const int gkc = tid >> 4;  // 0..15 : k row for G load
    const int giv = tid & 15;  // 0..15 : float4 index along i

    for (int k0 = 0; k0 < DD; k0 += KC) {
        __syncthreads();
        {
            // q-side tiles: one float4 per array per thread -> duplicated pairs
            float4 c  = *(const float4*)&d_C [(q0 + lq) * DD + k0 + 4 * lkv];
            float4 a2 = *(const float4*)&d_A2[(q0 + lq) * DD + k0 + 4 * lkv];
            float4 ab = *(const float4*)&d_AB[(q0 + lq) * DD + k0 + 4 * lkv];
            u64* pc = &sC [lq][4 * lkv];
            u64* pa = &sA2[lq][4 * lkv];
            u64* pb = &sAB[lq][4 * lkv];
            pc[0] = pack2(c.x,  c.x);  pc[1] = pack2(c.y,  c.y);
            pc[2] = pack2(c.z,  c.z);  pc[3] = pack2(c.w,  c.w);
            pa[0] = pack2(a2.x, a2.x); pa[1] = pack2(a2.y, a2.y);
            pa[2] = pack2(a2.z, a2.z); pa[3] = pack2(a2.w, a2.w);
            pb[0] = pack2(ab.x, ab.x); pb[1] = pack2(ab.y, ab.y);
            pb[2] = pack2(ab.z, ab.z); pb[3] = pack2(ab.w, ab.w);

            // G tile + squared copy
            float4 g = *(const float4*)&d_GT[(k0 + gkc) * II + i0 + 4 * giv];
            *(float4*)&sG[gkc][4 * giv] = g;
            float4 g2;
            g2.x = g.x * g.x; g2.y = g.y * g.y;
            g2.z = g.z * g.z; g2.w = g.w * g.w;
            *(float4*)&sG2[gkc][4 * giv] = g2;
        }
        __syncthreads();

        const u64* pC  = &sC [ty * 4][0];
        const u64* pA2 = &sA2[ty * 4][0];
        const u64* pAB = &sAB[ty * 4][0];

        #pragma unroll
        for (int kc = 0; kc < KC; kc++) {
            ulonglong2 gv  = *(const ulonglong2*)&sG [kc][tx * 4];
            ulonglong2 g2v = *(const ulonglong2*)&sG2[kc][tx * 4];
            #pragma unroll
            for (int u = 0; u < 4; u++) {
                u64 cu  = pC [u * QPITCH + kc];
                u64 a2u = pA2[u * QPITCH + kc];
                u64 abu = pAB[u * QPITCH + kc];
                FMA2(s1[u][0], cu,  gv.x);
                FMA2(s1[u][1], cu,  gv.y);
                FMA2(s2[u][0], a2u, g2v.x);
                FMA2(s2[u][1], a2u, g2v.y);
                FMA2(s2[u][0], abu, gv.x);
                FMA2(s2[u][1], abu, gv.y);
            }
        }
    }

    // epilogue: score = sigmoid((s1+c0) / max(sqrt(s2+b0), 1e-12))
    const float b0 = d_b0;
    #pragma unroll
    for (int u = 0; u < 4; u++) {
        int q = q0 + ty * 4 + u;
        float c0 = d_c0[q];
        float a[4], b[4];
        unpack2(s1[u][0], a[0], a[1]);
        unpack2(s1[u][1], a[2], a[3]);
        unpack2(s2[u][0], b[0], b[1]);
        unpack2(s2[u][1], b[2], b[3]);
        float4 r;
        float* rp = &r.x;
        #pragma unroll
        for (int v = 0; v < 4; v++) {
            float denom = fmaxf(sqrtf(b[v] + b0), 1e-12f);
            float val = (a[v] + c0) / denom;
            rp[v] = 1.f / (1.f + __expf(-val));
        }
        *(float4*)&out[q * II + i0 + tx * 4] = r;
    }
}

extern "C" void kernel_launch(void* const* d_in, const int* in_sizes, int n_in,
                              void* d_out, int out_size) {
    const float* query_feats       = (const float*)d_in[0];
    const float* query_img_feats   = (const float*)d_in[1];
    const float* gallery_img_feats = (const float*)d_in[2];
    const float* bn_gamma          = (const float*)d_in[3];
    const float* bn_beta           = (const float*)d_in[4];
    const float* bn_mean           = (const float*)d_in[5];
    const float* bn_var            = (const float*)d_in[6];
    float* out = (float*)d_out;

    prep_kernel<<<64, 256>>>(query_feats, query_img_feats, gallery_img_feats,
                             bn_gamma, bn_beta, bn_mean, bn_var);
    dim3 grid(II / BI, QD / BQ);
    score_kernel<<<grid, 256>>>(out);
}